// round 3
// baseline (speedup 1.0000x reference)
#include <cuda_runtime.h>
#include <cstdint>
#include <cstddef>

// ---------------- problem constants ----------------
#define B_     8
#define CIN    256
#define HH     128
#define WW     128
#define S_SP   16384      // H*W
#define O3     1536       // 3*INNER
#define INNER_ 512
#define NHEADS 8
#define DHEAD  64
#define FDIM   8192       // W*DHEAD == H*DHEAD
#define NTOK   128
#define NSPLIT 4
#define KSPLIT (FDIM / NSPLIT)   // 2048

// ---------------- scratch (device globals; no allocation allowed) ----------------
__device__ float g_qkv[(size_t)B_ * S_SP * O3];                    // (b, n_sp, o)   805 MB
__device__ float g_Spart[64 * 2 * NSPLIT * NTOK * NTOK];           // (gb*2+dir, split, i, j)
__device__ float g_P[64 * 2 * NTOK * NTOK];                        // (gb*2+dir, i, j)
__device__ float g_comb[(size_t)B_ * S_SP * INNER_];               // (b, n_sp, c2)  268 MB

// ---------------- tf32 helpers ----------------
__device__ __forceinline__ uint32_t f2tf(float f) {
    uint32_t u;
    asm("cvt.rna.tf32.f32 %0, %1;" : "=r"(u) : "f"(f));
    return u;
}

__device__ __forceinline__ void mma_tf32(float c[4],
                                         uint32_t a0, uint32_t a1, uint32_t a2, uint32_t a3,
                                         uint32_t b0, uint32_t b1) {
    asm volatile(
        "mma.sync.aligned.m16n8k8.row.col.f32.tf32.tf32.f32 "
        "{%0,%1,%2,%3}, {%4,%5,%6,%7}, {%8,%9}, {%0,%1,%2,%3};"
        : "+f"(c[0]), "+f"(c[1]), "+f"(c[2]), "+f"(c[3])
        : "r"(a0), "r"(a1), "r"(a2), "r"(a3), "r"(b0), "r"(b1));
}

// 128x128 CTA tile, 8 warps arranged 2x4, warp tile 64x32, BK=16 (2 k8 steps).
// As, Bs layout: [BK][128 + 4 pad], K-major.
__device__ __forceinline__ void tile_mma(const uint32_t (*As)[132], const uint32_t (*Bs)[132],
                                         float acc[4][4][4], int wm, int wn, int lane) {
    int g = lane >> 2, t = lane & 3;
#pragma unroll
    for (int ks = 0; ks < 2; ks++) {
        uint32_t a[4][4], b[4][2];
#pragma unroll
        for (int mt = 0; mt < 4; mt++) {
            int m0 = wm * 64 + mt * 16;
            a[mt][0] = As[ks * 8 + t][m0 + g];
            a[mt][1] = As[ks * 8 + t][m0 + g + 8];
            a[mt][2] = As[ks * 8 + t + 4][m0 + g];
            a[mt][3] = As[ks * 8 + t + 4][m0 + g + 8];
        }
#pragma unroll
        for (int nt = 0; nt < 4; nt++) {
            int n0 = wn * 32 + nt * 8;
            b[nt][0] = Bs[ks * 8 + t][n0 + g];
            b[nt][1] = Bs[ks * 8 + t + 4][n0 + g];
        }
#pragma unroll
        for (int mt = 0; mt < 4; mt++)
#pragma unroll
            for (int nt = 0; nt < 4; nt++)
                mma_tf32(acc[mt][nt], a[mt][0], a[mt][1], a[mt][2], a[mt][3],
                         b[nt][0], b[nt][1]);
    }
}

// ================= Kernel 1: QKV GEMM =================
// qkv[b][n_sp][o] = sum_c x[b][c][n_sp] * wqkv[o][c]
// grid (12 o-tiles, 128 nsp-tiles, 8 b), 256 threads
__global__ void qkv_gemm(const float* __restrict__ x, const float* __restrict__ wqkv) {
    __shared__ uint32_t As[16][132];
    __shared__ uint32_t Bs[16][132];
    int b = blockIdx.z;
    int m0 = blockIdx.y * 128;   // n_sp
    int n0 = blockIdx.x * 128;   // o
    int tid = threadIdx.x, lane = tid & 31, wid = tid >> 5;
    int wm = wid >> 2, wn = wid & 3;
    const float* xb = x + (size_t)b * CIN * S_SP;

    float acc[4][4][4];
#pragma unroll
    for (int i = 0; i < 4; i++)
#pragma unroll
        for (int j = 0; j < 4; j++)
#pragma unroll
            for (int r = 0; r < 4; r++) acc[i][j][r] = 0.f;

    for (int k0 = 0; k0 < CIN; k0 += 16) {
        // A: As[k][m] = x[b][k0+k][m0+m]  (m contiguous in gmem)
#pragma unroll
        for (int i = 0; i < 8; i++) {
            int idx = tid + i * 256;
            int k = idx >> 7, m = idx & 127;
            As[k][m] = f2tf(xb[(size_t)(k0 + k) * S_SP + m0 + m]);
        }
        // B: Bs[k][n] = wqkv[(n0+n)][k0+k]  (k contiguous in gmem)
#pragma unroll
        for (int i = 0; i < 8; i++) {
            int idx = tid + i * 256;
            int n = idx >> 4, kk = idx & 15;
            Bs[kk][n] = f2tf(wqkv[(size_t)(n0 + n) * CIN + k0 + kk]);
        }
        __syncthreads();
        tile_mma(As, Bs, acc, wm, wn, lane);
        __syncthreads();
    }

    int g = lane >> 2, t = lane & 3;
    float* outb = g_qkv + (size_t)b * S_SP * O3;
#pragma unroll
    for (int mt = 0; mt < 4; mt++)
#pragma unroll
        for (int nt = 0; nt < 4; nt++) {
            int row = wm * 64 + mt * 16 + g;
            int col = n0 + wn * 32 + nt * 8 + 2 * t;
            float2 v0 = make_float2(acc[mt][nt][0], acc[mt][nt][1]);
            float2 v1 = make_float2(acc[mt][nt][2], acc[mt][nt][3]);
            *(float2*)&outb[(size_t)(m0 + row) * O3 + col] = v0;
            *(float2*)&outb[(size_t)(m0 + row + 8) * O3 + col] = v1;
        }
}

// ================= Kernel 2: QK^T partial scores =================
// grid (NSPLIT, 64 gb, 2 dir), 256 threads. Full 128x128 S tile per CTA, K-range 2048.
__global__ void qk_gemm() {
    __shared__ uint32_t As[16][132];
    __shared__ uint32_t Bs[16][132];
    int split = blockIdx.x, gb = blockIdx.y, dir = blockIdx.z;
    int b = gb >> 3, head = gb & 7;
    int tid = threadIdx.x, lane = tid & 31, wid = tid >> 5;
    int wm = wid >> 2, wn = wid & 3;
    const float* qb = g_qkv + (size_t)b * S_SP * O3 + head * DHEAD;        // q at o-offset 0
    const float* kb = qb + INNER_;                                          // k at +512

    float acc[4][4][4];
#pragma unroll
    for (int i = 0; i < 4; i++)
#pragma unroll
        for (int j = 0; j < 4; j++)
#pragma unroll
            for (int r = 0; r < 4; r++) acc[i][j][r] = 0.f;

    int fbeg = split * KSPLIT;
    for (int f0 = fbeg; f0 < fbeg + KSPLIT; f0 += 16) {
        int fw = f0 >> 6;        // constant over the 16-chunk (16 | 64)
        int dbase = f0 & 63;
#pragma unroll
        for (int i = 0; i < 8; i++) {
            int idx = tid + i * 256;
            int m = idx >> 4, kk = idx & 15;
            int nsp = (dir == 0) ? (m * WW + fw) : (fw * WW + m);
            size_t a = (size_t)nsp * O3 + dbase + kk;
            As[kk][m] = f2tf(qb[a]);
            Bs[kk][m] = f2tf(kb[a]);
        }
        __syncthreads();
        tile_mma(As, Bs, acc, wm, wn, lane);
        __syncthreads();
    }

    int g = lane >> 2, t = lane & 3;
    float* sp = g_Spart + (size_t)((gb * 2 + dir) * NSPLIT + split) * NTOK * NTOK;
#pragma unroll
    for (int mt = 0; mt < 4; mt++)
#pragma unroll
        for (int nt = 0; nt < 4; nt++) {
            int row = wm * 64 + mt * 16 + g;
            int col = wn * 32 + nt * 8 + 2 * t;
            float2 v0 = make_float2(acc[mt][nt][0], acc[mt][nt][1]);
            float2 v1 = make_float2(acc[mt][nt][2], acc[mt][nt][3]);
            *(float2*)&sp[(size_t)row * NTOK + col] = v0;
            *(float2*)&sp[(size_t)(row + 8) * NTOK + col] = v1;
        }
}

// ================= Kernel 3: softmax =================
// grid (128 rows, 128 gbdir), 128 threads
__global__ void softmax_k() {
    int gbdir = blockIdx.y;
    int i = blockIdx.x;
    int j = threadIdx.x;
    const float* sp = g_Spart + (size_t)gbdir * NSPLIT * NTOK * NTOK + i * NTOK + j;
    float s = sp[0] + sp[NTOK * NTOK] + sp[2 * NTOK * NTOK] + sp[3 * NTOK * NTOK];
    s *= 0.125f;   // dim_head^-0.5

    __shared__ float red[4];
    float m = s;
#pragma unroll
    for (int off = 16; off; off >>= 1) m = fmaxf(m, __shfl_xor_sync(0xffffffffu, m, off));
    if ((j & 31) == 0) red[j >> 5] = m;
    __syncthreads();
    m = fmaxf(fmaxf(red[0], red[1]), fmaxf(red[2], red[3]));
    __syncthreads();

    float e = expf(s - m);
    float sum = e;
#pragma unroll
    for (int off = 16; off; off >>= 1) sum += __shfl_xor_sync(0xffffffffu, sum, off);
    if ((j & 31) == 0) red[j >> 5] = sum;
    __syncthreads();
    sum = red[0] + red[1] + red[2] + red[3];

    g_P[(size_t)gbdir * NTOK * NTOK + i * NTOK + j] = e / sum;
}

// ================= Kernel 4: O = P @ V =================
// grid (64 f-chunks, 64 gb), 256 threads. dir passed as arg; dir0 writes '=', dir1 '+='.
__global__ void av_gemm(int dir) {
    __shared__ uint32_t As[16][132];
    __shared__ uint32_t Bs[16][132];
    int gb = blockIdx.y;
    int b = gb >> 3, head = gb & 7;
    int f0base = blockIdx.x * 128;
    int tid = threadIdx.x, lane = tid & 31, wid = tid >> 5;
    int wm = wid >> 2, wn = wid & 3;
    const float* pmat = g_P + (size_t)(gb * 2 + dir) * NTOK * NTOK;
    const float* vb = g_qkv + (size_t)b * S_SP * O3 + 2 * INNER_ + head * DHEAD;

    float acc[4][4][4];
#pragma unroll
    for (int i = 0; i < 4; i++)
#pragma unroll
        for (int j = 0; j < 4; j++)
#pragma unroll
            for (int r = 0; r < 4; r++) acc[i][j][r] = 0.f;

    for (int k0 = 0; k0 < NTOK; k0 += 16) {
        // A: As[kk][m] = P[m][k0+kk]
#pragma unroll
        for (int i = 0; i < 8; i++) {
            int idx = tid + i * 256;
            int m = idx >> 4, kk = idx & 15;
            As[kk][m] = f2tf(pmat[(size_t)m * NTOK + k0 + kk]);
        }
        // B: Bs[kk][n] = V[token k0+kk][f0base+n]
#pragma unroll
        for (int i = 0; i < 8; i++) {
            int idx = tid + i * 256;
            int kk = idx >> 7, n = idx & 127;
            int f = f0base + n;
            int fw = f >> 6, d = f & 63;
            int j = k0 + kk;
            int nsp = (dir == 0) ? (j * WW + fw) : (fw * WW + j);
            Bs[kk][n] = f2tf(vb[(size_t)nsp * O3 + d]);
        }
        __syncthreads();
        tile_mma(As, Bs, acc, wm, wn, lane);
        __syncthreads();
    }

    int g = lane >> 2, t = lane & 3;
    float* cbase = g_comb + (size_t)b * S_SP * INNER_;
#pragma unroll
    for (int mt = 0; mt < 4; mt++)
#pragma unroll
        for (int nt = 0; nt < 4; nt++) {
            int row = wm * 64 + mt * 16 + g;         // token index i
            int col = wn * 32 + nt * 8 + 2 * t;      // feature within chunk (even)
            int f = f0base + col;
            int fw = f >> 6, d = f & 63;             // col even -> d, d+1 in same 64-block
#pragma unroll
            for (int half = 0; half < 2; half++) {
                int i_tok = row + half * 8;
                int nsp = (dir == 0) ? (i_tok * WW + fw) : (fw * WW + i_tok);
                float* p = &cbase[(size_t)nsp * INNER_ + head * DHEAD + d];
                float2 v = make_float2(0.5f * acc[mt][nt][half * 2],
                                       0.5f * acc[mt][nt][half * 2 + 1]);
                if (dir == 0) {
                    *(float2*)p = v;
                } else {
                    float2 o = *(const float2*)p;
                    o.x += v.x; o.y += v.y;
                    *(float2*)p = o;
                }
            }
        }
}

// ================= Kernel 5: output GEMM + bias + residual =================
// out[b][o2][n_sp] = sum_k comb[b][n_sp][k] * wout[o2][k] + bout[o2] + x[b][o2][n_sp]
// grid (128 nsp-tiles, 2 o2-tiles, 8 b), 256 threads. Rows = o2, Cols = n_sp.
__global__ void out_gemm(const float* __restrict__ x, const float* __restrict__ wout,
                         const float* __restrict__ bout, float* __restrict__ out) {
    __shared__ uint32_t As[16][132];
    __shared__ uint32_t Bs[16][132];
    int b = blockIdx.z;
    int m0 = blockIdx.y * 128;   // o2
    int n0 = blockIdx.x * 128;   // n_sp
    int tid = threadIdx.x, lane = tid & 31, wid = tid >> 5;
    int wm = wid >> 2, wn = wid & 3;
    const float* cb = g_comb + (size_t)b * S_SP * INNER_;

    float acc[4][4][4];
#pragma unroll
    for (int i = 0; i < 4; i++)
#pragma unroll
        for (int j = 0; j < 4; j++)
#pragma unroll
            for (int r = 0; r < 4; r++) acc[i][j][r] = 0.f;

    for (int k0 = 0; k0 < INNER_; k0 += 16) {
        // A: As[kk][m] = wout[(m0+m)][k0+kk]
#pragma unroll
        for (int i = 0; i < 8; i++) {
            int idx = tid + i * 256;
            int m = idx >> 4, kk = idx & 15;
            As[kk][m] = f2tf(wout[(size_t)(m0 + m) * INNER_ + k0 + kk]);
        }
        // B: Bs[kk][n] = comb[(n0+n)][k0+kk]
#pragma unroll
        for (int i = 0; i < 8; i++) {
            int idx = tid + i * 256;
            int n = idx >> 4, kk = idx & 15;
            Bs[kk][n] = f2tf(cb[(size_t)(n0 + n) * INNER_ + k0 + kk]);
        }
        __syncthreads();
        tile_mma(As, Bs, acc, wm, wn, lane);
        __syncthreads();
    }

    int g = lane >> 2, t = lane & 3;
#pragma unroll
    for (int mt = 0; mt < 4; mt++)
#pragma unroll
        for (int nt = 0; nt < 4; nt++) {
            int row = wm * 64 + mt * 16 + g;         // o2 within tile
            int col = n0 + wn * 32 + nt * 8 + 2 * t; // n_sp (even)
#pragma unroll
            for (int half = 0; half < 2; half++) {
                int o2 = m0 + row + half * 8;
                size_t addr = ((size_t)b * CIN + o2) * S_SP + col;
                float2 xr = *(const float2*)&x[addr];
                float bias = bout[o2];
                float2 v = make_float2(acc[mt][nt][half * 2] + bias + xr.x,
                                       acc[mt][nt][half * 2 + 1] + bias + xr.y);
                *(float2*)&out[addr] = v;
            }
        }
}

// ================= launch =================
extern "C" void kernel_launch(void* const* d_in, const int* in_sizes, int n_in,
                              void* d_out, int out_size) {
    (void)in_sizes; (void)n_in; (void)out_size;
    const float* x    = (const float*)d_in[0];
    const float* wqkv = (const float*)d_in[1];
    const float* wout = (const float*)d_in[2];
    const float* bout = (const float*)d_in[3];
    float* out = (float*)d_out;

    dim3 blk(256);
    qkv_gemm<<<dim3(O3 / 128, S_SP / 128, B_), blk>>>(x, wqkv);
    qk_gemm<<<dim3(NSPLIT, 64, 2), blk>>>();
    softmax_k<<<dim3(NTOK, 128), 128>>>();
    av_gemm<<<dim3(FDIM / 128, 64), blk>>>(0);
    av_gemm<<<dim3(FDIM / 128, 64), blk>>>(1);
    out_gemm<<<dim3(S_SP / 128, CIN / 128, B_), blk>>>(x, wout, bout, out);
}

// round 6
// speedup vs baseline: 1.2397x; 1.2397x over previous
#include <cuda_runtime.h>
#include <cstdint>
#include <cstddef>

// ---------------- problem constants ----------------
#define B_     8
#define CIN    256
#define HH     128
#define WW     128
#define S_SP   16384      // H*W
#define O3     1536       // 3*INNER
#define INNER_ 512
#define NHEADS 8
#define DHEAD  64
#define FDIM   8192       // W*DHEAD == H*DHEAD
#define NTOK   128
#define NSPLIT 4
#define KSPLIT (FDIM / NSPLIT)   // 2048

#define SMS 136           // smem row stride (words): 136 % 32 == 8 -> conflict-free frag LDS

// ---------------- scratch (device globals; no allocation allowed) ----------------
__device__ float g_qkv[(size_t)B_ * S_SP * O3];                    // (b, n_sp, o)
__device__ float g_Spart[64 * 2 * NSPLIT * NTOK * NTOK];           // (gb*2+dir, split, i, j)
__device__ float g_P[64 * 2 * NTOK * NTOK];                        // (gb*2+dir, i, j)
__device__ float g_comb0[(size_t)B_ * S_SP * INNER_];              // dir0 contribution
__device__ float g_comb1[(size_t)B_ * S_SP * INNER_];              // dir1 contribution

// ---------------- tf32 helpers ----------------
__device__ __forceinline__ uint32_t f2tf(float f) {
    uint32_t u;
    asm("cvt.rna.tf32.f32 %0, %1;" : "=r"(u) : "f"(f));
    return u;
}

__device__ __forceinline__ void mma_tf32(float c[4],
                                         uint32_t a0, uint32_t a1, uint32_t a2, uint32_t a3,
                                         uint32_t b0, uint32_t b1) {
    asm volatile(
        "mma.sync.aligned.m16n8k8.row.col.f32.tf32.tf32.f32 "
        "{%0,%1,%2,%3}, {%4,%5,%6,%7}, {%8,%9}, {%0,%1,%2,%3};"
        : "+f"(c[0]), "+f"(c[1]), "+f"(c[2]), "+f"(c[3])
        : "r"(a0), "r"(a1), "r"(a2), "r"(a3), "r"(b0), "r"(b1));
}

// 128x128 CTA tile, 8 warps 2x4, warp tile 64x32, BK=16 (2 k8 steps).
__device__ __forceinline__ void tile_mma(const uint32_t (*As)[SMS], const uint32_t (*Bs)[SMS],
                                         float acc[4][4][4], int wm, int wn, int lane) {
    int g = lane >> 2, t = lane & 3;
#pragma unroll
    for (int ks = 0; ks < 2; ks++) {
        uint32_t a[4][4], b[4][2];
#pragma unroll
        for (int mt = 0; mt < 4; mt++) {
            int m0 = wm * 64 + mt * 16;
            a[mt][0] = As[ks * 8 + t][m0 + g];
            a[mt][1] = As[ks * 8 + t][m0 + g + 8];
            a[mt][2] = As[ks * 8 + t + 4][m0 + g];
            a[mt][3] = As[ks * 8 + t + 4][m0 + g + 8];
        }
#pragma unroll
        for (int nt = 0; nt < 4; nt++) {
            int n0 = wn * 32 + nt * 8;
            b[nt][0] = Bs[ks * 8 + t][n0 + g];
            b[nt][1] = Bs[ks * 8 + t + 4][n0 + g];
        }
#pragma unroll
        for (int mt = 0; mt < 4; mt++)
#pragma unroll
            for (int nt = 0; nt < 4; nt++)
                mma_tf32(acc[mt][nt], a[mt][0], a[mt][1], a[mt][2], a[mt][3],
                         b[nt][0], b[nt][1]);
    }
}

#define ZERO_ACC(acc)                                  \
    _Pragma("unroll") for (int i = 0; i < 4; i++)      \
    _Pragma("unroll") for (int j = 0; j < 4; j++)      \
    _Pragma("unroll") for (int r = 0; r < 4; r++) acc[i][j][r] = 0.f;

// ================= Kernel 1: QKV GEMM =================
// qkv[b][n_sp][o] = sum_c x[b][c][n_sp] * wqkv[o][c]
__global__ __launch_bounds__(256, 2) void qkv_gemm(const float* __restrict__ x,
                                                   const float* __restrict__ wqkv) {
    __shared__ uint32_t As[2][16][SMS];
    __shared__ uint32_t Bs[2][16][SMS];
    int b = blockIdx.z;
    int m0 = blockIdx.y * 128;   // n_sp
    int n0 = blockIdx.x * 128;   // o
    int tid = threadIdx.x, lane = tid & 31, wid = tid >> 5;
    int wm = wid >> 2, wn = wid & 3;
    const float* xb = x + (size_t)b * CIN * S_SP;

    float acc[4][4][4];
    ZERO_ACC(acc);

    float ra[8], rb[8];
    // prefetch k0 = 0
#pragma unroll
    for (int i = 0; i < 8; i++) {
        int idx = tid + i * 256;
        int k = idx >> 7, m = idx & 127;
        ra[i] = xb[(size_t)k * S_SP + m0 + m];
        int n = idx >> 4, kk = idx & 15;
        rb[i] = wqkv[(size_t)(n0 + n) * CIN + kk];
    }

    int buf = 0;
    for (int k0 = 0; k0 < CIN; k0 += 16) {
#pragma unroll
        for (int i = 0; i < 8; i++) {
            int idx = tid + i * 256;
            int k = idx >> 7, m = idx & 127;
            As[buf][k][m] = f2tf(ra[i]);
            int n = idx >> 4, kk = idx & 15;
            Bs[buf][kk][n] = f2tf(rb[i]);
        }
        __syncthreads();
        if (k0 + 16 < CIN) {
#pragma unroll
            for (int i = 0; i < 8; i++) {
                int idx = tid + i * 256;
                int k = idx >> 7, m = idx & 127;
                ra[i] = xb[(size_t)(k0 + 16 + k) * S_SP + m0 + m];
                int n = idx >> 4, kk = idx & 15;
                rb[i] = wqkv[(size_t)(n0 + n) * CIN + k0 + 16 + kk];
            }
        }
        tile_mma(As[buf], Bs[buf], acc, wm, wn, lane);
        buf ^= 1;
    }

    int g = lane >> 2, t = lane & 3;
    float* outb = g_qkv + (size_t)b * S_SP * O3;
#pragma unroll
    for (int mt = 0; mt < 4; mt++)
#pragma unroll
        for (int nt = 0; nt < 4; nt++) {
            int row = wm * 64 + mt * 16 + g;
            int col = n0 + wn * 32 + nt * 8 + 2 * t;
            float2 v0 = make_float2(acc[mt][nt][0], acc[mt][nt][1]);
            float2 v1 = make_float2(acc[mt][nt][2], acc[mt][nt][3]);
            *(float2*)&outb[(size_t)(m0 + row) * O3 + col] = v0;
            *(float2*)&outb[(size_t)(m0 + row + 8) * O3 + col] = v1;
        }
}

// ================= Kernel 2: QK^T partial scores =================
__global__ __launch_bounds__(256, 2) void qk_gemm() {
    __shared__ uint32_t As[2][16][SMS];
    __shared__ uint32_t Bs[2][16][SMS];
    int split = blockIdx.x, gb = blockIdx.y, dir = blockIdx.z;
    int b = gb >> 3, head = gb & 7;
    int tid = threadIdx.x, lane = tid & 31, wid = tid >> 5;
    int wm = wid >> 2, wn = wid & 3;
    const float* qb = g_qkv + (size_t)b * S_SP * O3 + head * DHEAD;
    const float* kb = qb + INNER_;

    float acc[4][4][4];
    ZERO_ACC(acc);

    int fbeg = split * KSPLIT;
    int fend = fbeg + KSPLIT;

    float ra[8], rb[8];
    {
        int f0 = fbeg;
        int fw = f0 >> 6, dbase = f0 & 63;
#pragma unroll
        for (int i = 0; i < 8; i++) {
            int idx = tid + i * 256;
            int m = idx >> 4, kk = idx & 15;
            int nsp = (dir == 0) ? (m * WW + fw) : (fw * WW + m);
            size_t a = (size_t)nsp * O3 + dbase + kk;
            ra[i] = qb[a];
            rb[i] = kb[a];
        }
    }

    int buf = 0;
    for (int f0 = fbeg; f0 < fend; f0 += 16) {
#pragma unroll
        for (int i = 0; i < 8; i++) {
            int idx = tid + i * 256;
            int m = idx >> 4, kk = idx & 15;
            As[buf][kk][m] = f2tf(ra[i]);
            Bs[buf][kk][m] = f2tf(rb[i]);
        }
        __syncthreads();
        if (f0 + 16 < fend) {
            int fn = f0 + 16;
            int fw = fn >> 6, dbase = fn & 63;
#pragma unroll
            for (int i = 0; i < 8; i++) {
                int idx = tid + i * 256;
                int m = idx >> 4, kk = idx & 15;
                int nsp = (dir == 0) ? (m * WW + fw) : (fw * WW + m);
                size_t a = (size_t)nsp * O3 + dbase + kk;
                ra[i] = qb[a];
                rb[i] = kb[a];
            }
        }
        tile_mma(As[buf], Bs[buf], acc, wm, wn, lane);
        buf ^= 1;
    }

    int g = lane >> 2, t = lane & 3;
    float* sp = g_Spart + (size_t)((gb * 2 + dir) * NSPLIT + split) * NTOK * NTOK;
#pragma unroll
    for (int mt = 0; mt < 4; mt++)
#pragma unroll
        for (int nt = 0; nt < 4; nt++) {
            int row = wm * 64 + mt * 16 + g;
            int col = wn * 32 + nt * 8 + 2 * t;
            float2 v0 = make_float2(acc[mt][nt][0], acc[mt][nt][1]);
            float2 v1 = make_float2(acc[mt][nt][2], acc[mt][nt][3]);
            *(float2*)&sp[(size_t)row * NTOK + col] = v0;
            *(float2*)&sp[(size_t)(row + 8) * NTOK + col] = v1;
        }
}

// ================= Kernel 3: softmax =================
__global__ void softmax_k() {
    int gbdir = blockIdx.y;
    int i = blockIdx.x;
    int j = threadIdx.x;
    const float* sp = g_Spart + (size_t)gbdir * NSPLIT * NTOK * NTOK + i * NTOK + j;
    float s = sp[0] + sp[NTOK * NTOK] + sp[2 * NTOK * NTOK] + sp[3 * NTOK * NTOK];
    s *= 0.125f;

    __shared__ float red[4];
    float m = s;
#pragma unroll
    for (int off = 16; off; off >>= 1) m = fmaxf(m, __shfl_xor_sync(0xffffffffu, m, off));
    if ((j & 31) == 0) red[j >> 5] = m;
    __syncthreads();
    m = fmaxf(fmaxf(red[0], red[1]), fmaxf(red[2], red[3]));
    __syncthreads();

    float e = expf(s - m);
    float sum = e;
#pragma unroll
    for (int off = 16; off; off >>= 1) sum += __shfl_xor_sync(0xffffffffu, sum, off);
    if ((j & 31) == 0) red[j >> 5] = sum;
    __syncthreads();
    sum = red[0] + red[1] + red[2] + red[3];

    g_P[(size_t)gbdir * NTOK * NTOK + i * NTOK + j] = e / sum;
}

// ================= Kernel 4: O = P @ V (both dirs in one launch) =================
__global__ __launch_bounds__(256, 2) void av_gemm() {
    __shared__ uint32_t As[2][16][SMS];
    __shared__ uint32_t Bs[2][16][SMS];
    int gb = blockIdx.y, dir = blockIdx.z;
    int b = gb >> 3, head = gb & 7;
    int f0base = blockIdx.x * 128;
    int tid = threadIdx.x, lane = tid & 31, wid = tid >> 5;
    int wm = wid >> 2, wn = wid & 3;
    const float* pmat = g_P + (size_t)(gb * 2 + dir) * NTOK * NTOK;
    const float* vb = g_qkv + (size_t)b * S_SP * O3 + 2 * INNER_ + head * DHEAD;

    float acc[4][4][4];
    ZERO_ACC(acc);

    float ra[8], rb[8];
#pragma unroll
    for (int i = 0; i < 8; i++) {
        int idx = tid + i * 256;
        int m = idx >> 4, kk = idx & 15;
        ra[i] = pmat[(size_t)m * NTOK + kk];
        int kv = idx >> 7, n = idx & 127;
        int f = f0base + n;
        int fw = f >> 6, d = f & 63;
        int nsp = (dir == 0) ? (kv * WW + fw) : (fw * WW + kv);
        rb[i] = vb[(size_t)nsp * O3 + d];
    }

    int buf = 0;
    for (int k0 = 0; k0 < NTOK; k0 += 16) {
#pragma unroll
        for (int i = 0; i < 8; i++) {
            int idx = tid + i * 256;
            int m = idx >> 4, kk = idx & 15;
            As[buf][kk][m] = f2tf(ra[i]);
            int kv = idx >> 7, n = idx & 127;
            Bs[buf][kv][n] = f2tf(rb[i]);
        }
        __syncthreads();
        if (k0 + 16 < NTOK) {
#pragma unroll
            for (int i = 0; i < 8; i++) {
                int idx = tid + i * 256;
                int m = idx >> 4, kk = idx & 15;
                ra[i] = pmat[(size_t)m * NTOK + k0 + 16 + kk];
                int kv = idx >> 7, n = idx & 127;
                int f = f0base + n;
                int fw = f >> 6, d = f & 63;
                int j = k0 + 16 + kv;
                int nsp = (dir == 0) ? (j * WW + fw) : (fw * WW + j);
                rb[i] = vb[(size_t)nsp * O3 + d];
            }
        }
        tile_mma(As[buf], Bs[buf], acc, wm, wn, lane);
        buf ^= 1;
    }

    int g = lane >> 2, t = lane & 3;
    float* cbase = (dir == 0 ? g_comb0 : g_comb1) + (size_t)b * S_SP * INNER_;
#pragma unroll
    for (int mt = 0; mt < 4; mt++)
#pragma unroll
        for (int nt = 0; nt < 4; nt++) {
            int row = wm * 64 + mt * 16 + g;
            int col = wn * 32 + nt * 8 + 2 * t;
            int f = f0base + col;
            int fw = f >> 6, d = f & 63;
#pragma unroll
            for (int half = 0; half < 2; half++) {
                int i_tok = row + half * 8;
                int nsp = (dir == 0) ? (i_tok * WW + fw) : (fw * WW + i_tok);
                float* p = &cbase[(size_t)nsp * INNER_ + head * DHEAD + d];
                float2 v = make_float2(0.5f * acc[mt][nt][half * 2],
                                       0.5f * acc[mt][nt][half * 2 + 1]);
                *(float2*)p = v;
            }
        }
}

// ================= Kernel 5: output GEMM + bias + residual =================
__global__ __launch_bounds__(256, 2) void out_gemm(const float* __restrict__ x,
                                                   const float* __restrict__ wout,
                                                   const float* __restrict__ bout,
                                                   float* __restrict__ out) {
    __shared__ uint32_t As[2][16][SMS];
    __shared__ uint32_t Bs[2][16][SMS];
    int b = blockIdx.z;
    int m0 = blockIdx.y * 128;   // o2
    int n0 = blockIdx.x * 128;   // n_sp
    int tid = threadIdx.x, lane = tid & 31, wid = tid >> 5;
    int wm = wid >> 2, wn = wid & 3;
    const float* c0 = g_comb0 + (size_t)b * S_SP * INNER_;
    const float* c1 = g_comb1 + (size_t)b * S_SP * INNER_;

    float acc[4][4][4];
    ZERO_ACC(acc);

    float ra[8], rb[8];
#pragma unroll
    for (int i = 0; i < 8; i++) {
        int idx = tid + i * 256;
        int m = idx >> 4, kk = idx & 15;
        ra[i] = wout[(size_t)(m0 + m) * INNER_ + kk];
        size_t a = (size_t)(n0 + m) * INNER_ + kk;
        rb[i] = c0[a] + c1[a];
    }

    int buf = 0;
    for (int k0 = 0; k0 < INNER_; k0 += 16) {
#pragma unroll
        for (int i = 0; i < 8; i++) {
            int idx = tid + i * 256;
            int m = idx >> 4, kk = idx & 15;
            As[buf][kk][m] = f2tf(ra[i]);
            Bs[buf][kk][m] = f2tf(rb[i]);
        }
        __syncthreads();
        if (k0 + 16 < INNER_) {
#pragma unroll
            for (int i = 0; i < 8; i++) {
                int idx = tid + i * 256;
                int m = idx >> 4, kk = idx & 15;
                ra[i] = wout[(size_t)(m0 + m) * INNER_ + k0 + 16 + kk];
                size_t a = (size_t)(n0 + m) * INNER_ + k0 + 16 + kk;
                rb[i] = c0[a] + c1[a];
            }
        }
        tile_mma(As[buf], Bs[buf], acc, wm, wn, lane);
        buf ^= 1;
    }

    int g = lane >> 2, t = lane & 3;
#pragma unroll
    for (int mt = 0; mt < 4; mt++)
#pragma unroll
        for (int nt = 0; nt < 4; nt++) {
            int row = wm * 64 + mt * 16 + g;
            int col = n0 + wn * 32 + nt * 8 + 2 * t;
#pragma unroll
            for (int half = 0; half < 2; half++) {
                int o2 = m0 + row + half * 8;
                size_t addr = ((size_t)b * CIN + o2) * S_SP + col;
                float2 xr = *(const float2*)&x[addr];
                float bias = bout[o2];
                float2 v = make_float2(acc[mt][nt][half * 2] + bias + xr.x,
                                       acc[mt][nt][half * 2 + 1] + bias + xr.y);
                *(float2*)&out[addr] = v;
            }
        }
}

// ================= launch =================
extern "C" void kernel_launch(void* const* d_in, const int* in_sizes, int n_in,
                              void* d_out, int out_size) {
    (void)in_sizes; (void)n_in; (void)out_size;
    const float* x    = (const float*)d_in[0];
    const float* wqkv = (const float*)d_in[1];
    const float* wout = (const float*)d_in[2];
    const float* bout = (const float*)d_in[3];
    float* out = (float*)d_out;

    dim3 blk(256);
    qkv_gemm<<<dim3(O3 / 128, S_SP / 128, B_), blk>>>(x, wqkv);
    qk_gemm<<<dim3(NSPLIT, 64, 2), blk>>>();
    softmax_k<<<dim3(NTOK, 128), 128>>>();
    av_gemm<<<dim3(FDIM / 128, 64, 2), blk>>>();
    out_gemm<<<dim3(S_SP / 128, CIN / 128, B_), blk>>>(x, wout, bout, out);
}